// round 4
// baseline (speedup 1.0000x reference)
#include <cuda_runtime.h>
#include <cuda_bf16.h>
#include <cstdint>

// ROI Align (torchvision semantics), OUT 7x7, adaptive grid <= 4x4.
// features: [B=4, C=256, H=200, W=272] fp32 NCHW
// rois:     [N=512, 5] (b, x1, y1, x2, y2) fp32
// out:      [N, C, 7, 7] fp32
//
// R4: 16B cp.async.cg staging into [c][row][col] SMEM (bank-safe pitches),
// precomputed per-axis tap offsets, L2-friendly block order (channel-slice
// major so overlapping ROIs hit L2).

#define OUT_H 7
#define OUT_W 7
#define NBINS 49
#define MAXG  4
#define C_TILE 8
#define REG   30               // region rows per axis (roi dims <= 28)
#define RPITCH 36              // floats per staged row (9 x 16B chunks)
#define CPITCH 1092            // floats per channel: 30*36 + 12 pad; 1092 % 32 == 4
                               // -> the 8 channel lanes map to 8 distinct banks

#define FEAT_C 256
#define FEAT_H 200
#define FEAT_W 272
#define FEAT_HW (FEAT_H * FEAT_W)

#define SMEM_REGION_FLOATS (C_TILE * CPITCH)       // 8736
#define SMEM_OUT_FLOATS    (C_TILE * NBINS)        // 392
#define SMEM_W_FLOATS      (8 * OUT_H * MAXG)      // 224 (4 float + 4 int arrays of 28)
#define SMEM_TOTAL_BYTES   ((SMEM_REGION_FLOATS + SMEM_OUT_FLOATS + SMEM_W_FLOATS) * 4)

__device__ __forceinline__ uint32_t smem_u32(const void* p) {
    uint32_t a;
    asm("{ .reg .u64 t; cvta.to.shared.u64 t, %1; cvt.u32.u64 %0, t; }"
        : "=r"(a) : "l"(p));
    return a;
}

__device__ __forceinline__ void cp_async16(uint32_t dst, const void* src, int src_bytes) {
    asm volatile("cp.async.cg.shared.global [%0], [%1], 16, %2;\n"
                 :: "r"(dst), "l"(src), "r"(src_bytes));
}

__global__ __launch_bounds__(256)
void roi_align_kernel(const float* __restrict__ feat,
                      const float* __restrict__ rois,
                      float* __restrict__ out)
{
    extern __shared__ float smem[];
    float* region = smem;                                   // [c][row][col]
    float* s_out  = region + SMEM_REGION_FLOATS;            // [c][bin]
    float* s_wy0  = s_out + SMEM_OUT_FLOATS;                // [28] each
    float* s_wy1  = s_wy0 + OUT_H * MAXG;
    float* s_wx0  = s_wy1 + OUT_H * MAXG;
    float* s_wx1  = s_wx0 + OUT_H * MAXG;
    int*   s_ryl  = (int*)(s_wx1 + OUT_H * MAXG);           // rl * RPITCH
    int*   s_ryh  = s_ryl + OUT_H * MAXG;                   // rh * RPITCH
    int*   s_cl   = s_ryh + OUT_H * MAXG;                   // col offset lo
    int*   s_ch   = s_cl  + OUT_H * MAXG;                   // col offset hi

    const int H = FEAT_H, W = FEAT_W;
    const int blk = blockIdx.x;
    const int n   = blk & 511;        // roi index
    const int ct  = blk >> 9;         // channel tile (slice-major for L2 reuse)

    const float* r = rois + n * 5;
    const int   bidx  = (int)r[0];
    const float x1    = r[1];
    const float y1    = r[2];
    const float roi_w = fmaxf(r[3] - x1, 1.0f);
    const float roi_h = fmaxf(r[4] - y1, 1.0f);
    const float bin_h = roi_h * (1.0f / OUT_H);
    const float bin_w = roi_w * (1.0f / OUT_W);
    int gh = (int)ceilf(roi_h * (1.0f / OUT_H)); gh = min(max(gh, 1), MAXG);
    int gw = (int)ceilf(roi_w * (1.0f / OUT_W)); gw = min(max(gw, 1), MAXG);

    const int ry0 = min(max((int)floorf(y1), 0), H - 1);
    const int rx0 = min(max((int)floorf(x1), 0), W - 1);
    const int ax0 = rx0 & ~3;                 // 16B-aligned window start

    const int tid  = threadIdx.x;

    // ---- phase 0: per-axis interp weights + precomputed region offsets ----
    if (tid < 2 * OUT_H * MAXG) {
        const bool isx = (tid >= OUT_H * MAXG);
        const int  t   = isx ? tid - OUT_H * MAXG : tid;
        const int  p   = t >> 2;          // output bin index along axis
        const int  gg  = t & 3;           // grid slot
        const float start = isx ? x1 : y1;
        const float binsz = isx ? bin_w : bin_h;
        const int   gcnt  = isx ? gw : gh;
        const int   size  = isx ? W : H;
        const float pos = start + (float)p * binsz + ((float)gg + 0.5f) * binsz / (float)gcnt;
        const bool valid = (pos >= -1.0f) && (pos <= (float)size);
        float pp = fmaxf(pos, 0.0f);
        int low = min((int)floorf(pp), size - 1);
        if (low >= size - 1) pp = (float)(size - 1);
        const float frac = pp - (float)low;
        const float m = valid ? 1.0f : 0.0f;
        const int hi = min(low + 1, size - 1);
        if (isx) {
            s_wx0[t] = (1.0f - frac) * m; s_wx1[t] = frac * m;
            s_cl[t] = min(max(low - ax0, 0), RPITCH - 1);
            s_ch[t] = min(max(hi  - ax0, 0), RPITCH - 1);
        } else {
            s_wy0[t] = (1.0f - frac) * m; s_wy1[t] = frac * m;
            s_ryl[t] = min(max(low - ry0, 0), REG - 1) * RPITCH;
            s_ryh[t] = min(max(hi  - ry0, 0), REG - 1) * RPITCH;
        }
    }

    // ---- phase 1: stage region via 16B cp.async.cg ----
    {
        const float* fb = feat + ((size_t)bidx * FEAT_C + (size_t)ct * C_TILE) * (size_t)FEAT_HW;
        const uint32_t sbase = smem_u32(region);
        // 240 rows (c,row) x 9 chunks of 16B
        #pragma unroll
        for (int it = 0; it < 9; ++it) {
            const int j = tid + it * 256;
            if (j < C_TILE * REG * 9) {
                const int row_id = j / 9;           // 0..239
                const int k      = j - row_id * 9;  // 16B chunk within row
                const int c      = row_id / REG;
                const int row    = row_id - c * REG;
                const int gy     = min(ry0 + row, H - 1);
                const int gxs    = ax0 + k * 4;
                const int nbytes = min(16, (W - gxs) * 4);   // >=0; zero-fill tail
                const float* src = fb + (size_t)c * FEAT_HW + (size_t)gy * W + gxs;
                cp_async16(sbase + (uint32_t)(c * CPITCH + row * RPITCH + k * 4) * 4u,
                           src, nbytes);
            }
        }
        asm volatile("cp.async.commit_group;\n" ::: "memory");
        asm volatile("cp.async.wait_group 0;\n" ::: "memory");
    }
    __syncthreads();

    // ---- phase 2: compute bins from SMEM ----
    {
        const int c   = tid & (C_TILE - 1);
        const int grp = tid >> 3;             // 32 bin groups
        const float inv = 1.0f / (float)max(gh * gw, 1);
        const float* regc = region + c * CPITCH;
        for (int bin = grp; bin < NBINS; bin += 32) {
            const int ph = bin / OUT_W;
            const int pw = bin - ph * OUT_W;
            float acc = 0.0f;
            for (int iy = 0; iy < gh; ++iy) {
                const int yi = ph * MAXG + iy;
                const float* rlo = regc + s_ryl[yi];
                const float* rhi = regc + s_ryh[yi];
                const float wy0 = s_wy0[yi];
                const float wy1 = s_wy1[yi];
                for (int ix = 0; ix < gw; ++ix) {
                    const int xi = pw * MAXG + ix;
                    const int cl = s_cl[xi];
                    const int ch = s_ch[xi];
                    const float wx0 = s_wx0[xi];
                    const float wx1 = s_wx1[xi];
                    const float v00 = rlo[cl];
                    const float v01 = rlo[ch];
                    const float v10 = rhi[cl];
                    const float v11 = rhi[ch];
                    acc += wy0 * (wx0 * v00 + wx1 * v01) + wy1 * (wx0 * v10 + wx1 * v11);
                }
            }
            s_out[c * NBINS + bin] = acc * inv;
        }
    }
    __syncthreads();

    // ---- phase 3: coalesced output write ----
    {
        float* ob = out + ((size_t)n * FEAT_C + (size_t)ct * C_TILE) * NBINS;
        for (int i = tid; i < C_TILE * NBINS; i += 256)
            ob[i] = s_out[i];
    }
}

extern "C" void kernel_launch(void* const* d_in, const int* in_sizes, int n_in,
                              void* d_out, int out_size)
{
    const float* feat = (const float*)d_in[0];
    const float* rois = (const float*)d_in[1];
    float* out = (float*)d_out;
    const int N = in_sizes[1] / 5;

    cudaFuncSetAttribute(roi_align_kernel,
                         cudaFuncAttributeMaxDynamicSharedMemorySize,
                         SMEM_TOTAL_BYTES);
    roi_align_kernel<<<N * (FEAT_C / C_TILE), 256, SMEM_TOTAL_BYTES>>>(feat, rois, out);
}

// round 5
// speedup vs baseline: 1.3215x; 1.3215x over previous
#include <cuda_runtime.h>
#include <cuda_bf16.h>
#include <cstdint>

// ROI Align (torchvision semantics), OUT 7x7, adaptive grid <= 4x4.
// features: [B=4, C=256, H=200, W=272] fp32 NCHW
// rois:     [N=512, 5] (b, x1, y1, x2, y2) fp32
// out:      [N, C, 7, 7] fp32
//
// R5: issue-bound optimization. warp=channel staging (no index divisions),
// float4-packed per-axis meta (1 LDS.128 per tap axis instead of 4 LDS.32 +
// min/max ALU), slice-major block order for L2 reuse, float4 output copy.

#define OUT_H 7
#define OUT_W 7
#define NBINS 49
#define MAXG  4
#define C_TILE 8
#define REG   30               // region extent per axis (roi dims <= 28 -> 30 taps)
#define PSTRIDE 9              // [pos][c] layout, c-pad to 9
#define ROWOFF (REG * PSTRIDE) // 270 floats per region row

#define FEAT_C 256
#define FEAT_H 200
#define FEAT_W 272
#define FEAT_HW (FEAT_H * FEAT_W)

#define SMEM_REGION_FLOATS (REG * REG * PSTRIDE)   // 8100
#define SMEM_OUT_FLOATS    (C_TILE * NBINS)        // 392
#define SMEM_META_FLOATS   (2 * OUT_H * MAXG * 4)  // 224 (two float4[28] arrays)
#define SMEM_TOTAL_BYTES   ((SMEM_REGION_FLOATS + SMEM_OUT_FLOATS + SMEM_META_FLOATS) * 4)

__device__ __forceinline__ uint32_t smem_u32(const void* p) {
    uint32_t a;
    asm("{ .reg .u64 t; cvta.to.shared.u64 t, %1; cvt.u32.u64 %0, t; }"
        : "=r"(a) : "l"(p));
    return a;
}

__device__ __forceinline__ void cp_async4(uint32_t dst, const void* src, int src_bytes) {
    asm volatile("cp.async.ca.shared.global [%0], [%1], 4, %2;\n"
                 :: "r"(dst), "l"(src), "r"(src_bytes));
}

__global__ __launch_bounds__(256)
void roi_align_kernel(const float* __restrict__ feat,
                      const float* __restrict__ rois,
                      float* __restrict__ out)
{
    extern __shared__ float smem[];
    float*  region  = smem;                              // [pos][c], pos = row*30+col
    float*  s_out   = region + SMEM_REGION_FLOATS;       // [c][bin]
    float4* s_ymeta = (float4*)(s_out + SMEM_OUT_FLOATS);   // [7*4]: wy0, wy1, rl*270, rh*270
    float4* s_xmeta = s_ymeta + OUT_H * MAXG;               // [7*4]: wx0, wx1, cl*9,  ch*9

    const int H = FEAT_H, W = FEAT_W;
    const int blk = blockIdx.x;
    const int n   = blk & 511;        // roi index
    const int ct  = blk >> 9;         // channel tile (slice-major for L2 reuse)

    const float* r = rois + n * 5;
    const int   bidx  = (int)r[0];
    const float x1    = r[1];
    const float y1    = r[2];
    const float roi_w = fmaxf(r[3] - x1, 1.0f);
    const float roi_h = fmaxf(r[4] - y1, 1.0f);
    const float bin_h = roi_h * (1.0f / OUT_H);
    const float bin_w = roi_w * (1.0f / OUT_W);
    int gh = (int)ceilf(roi_h * (1.0f / OUT_H)); gh = min(max(gh, 1), MAXG);
    int gw = (int)ceilf(roi_w * (1.0f / OUT_W)); gw = min(max(gw, 1), MAXG);

    const int ry0 = min(max((int)floorf(y1), 0), H - 1);
    const int rx0 = min(max((int)floorf(x1), 0), W - 1);

    const int tid  = threadIdx.x;
    const int lane = tid & 31;
    const int warp = tid >> 5;

    // ---- phase 0: per-axis interp weights + premultiplied offsets (float4) ----
    if (tid < 2 * OUT_H * MAXG) {
        const bool isx = (tid >= OUT_H * MAXG);
        const int  t   = isx ? tid - OUT_H * MAXG : tid;
        const int  p   = t >> 2;          // output bin index along axis
        const int  gg  = t & 3;           // grid slot
        const float start = isx ? x1 : y1;
        const float binsz = isx ? bin_w : bin_h;
        const int   gcnt  = isx ? gw : gh;
        const int   size  = isx ? W : H;
        const float pos = start + (float)p * binsz + ((float)gg + 0.5f) * binsz / (float)gcnt;
        const bool valid = (pos >= -1.0f) && (pos <= (float)size);
        float pp = fmaxf(pos, 0.0f);
        int low = min((int)floorf(pp), size - 1);
        if (low >= size - 1) pp = (float)(size - 1);
        const float frac = pp - (float)low;
        const float m = valid ? 1.0f : 0.0f;
        const int hi = min(low + 1, size - 1);
        float4 mv;
        mv.x = (1.0f - frac) * m;
        mv.y = frac * m;
        if (isx) {
            mv.z = __int_as_float(min(max(low - rx0, 0), REG - 1) * PSTRIDE);
            mv.w = __int_as_float(min(max(hi  - rx0, 0), REG - 1) * PSTRIDE);
            s_xmeta[t] = mv;
        } else {
            mv.z = __int_as_float(min(max(low - ry0, 0), REG - 1) * ROWOFF);
            mv.w = __int_as_float(min(max(hi  - ry0, 0), REG - 1) * ROWOFF);
            s_ymeta[t] = mv;
        }
    }

    // ---- phase 1: stage region, warp = channel, lanes = columns ----
    {
        const float* fb = feat
            + ((size_t)bidx * FEAT_C + (size_t)(ct * C_TILE + warp)) * (size_t)FEAT_HW;
        const uint32_t sbase = smem_u32(region);
        if (lane < REG) {
            const int  gx   = rx0 + lane;
            const bool xok  = (gx < W);
            const int  gxc  = min(gx, W - 1);
            const uint32_t dst0 = sbase + (uint32_t)((lane * PSTRIDE + warp) * 4);
            #pragma unroll
            for (int row = 0; row < REG; ++row) {
                const int  gy = ry0 + row;
                const bool ok = xok && (gy < H);
                const float* src = fb + (size_t)min(gy, H - 1) * W + gxc;
                cp_async4(dst0 + (uint32_t)(row * ROWOFF * 4), src, ok ? 4 : 0);
            }
        }
        asm volatile("cp.async.commit_group;\n" ::: "memory");
        asm volatile("cp.async.wait_group 0;\n" ::: "memory");
    }
    __syncthreads();

    // ---- phase 2: compute bins from SMEM (packed meta) ----
    {
        const int c   = tid & (C_TILE - 1);
        const int grp = tid >> 3;             // 32 bin groups
        const float inv = 1.0f / (float)max(gh * gw, 1);
        const float* regc = region + c;
        for (int bin = grp; bin < NBINS; bin += 32) {
            const int ph = bin / OUT_W;
            const int pw = bin - ph * OUT_W;
            const float4* ym = s_ymeta + ph * MAXG;
            const float4* xm = s_xmeta + pw * MAXG;
            float acc = 0.0f;
            for (int iy = 0; iy < gh; ++iy) {
                const float4 my = ym[iy];
                const float* rlo = regc + __float_as_int(my.z);
                const float* rhi = regc + __float_as_int(my.w);
                for (int ix = 0; ix < gw; ++ix) {
                    const float4 mx = xm[ix];
                    const int cl = __float_as_int(mx.z);
                    const int ch = __float_as_int(mx.w);
                    const float t0 = mx.x * rlo[cl] + mx.y * rlo[ch];
                    const float t1 = mx.x * rhi[cl] + mx.y * rhi[ch];
                    acc += my.x * t0 + my.y * t1;
                }
            }
            s_out[c * NBINS + bin] = acc * inv;
        }
    }
    __syncthreads();

    // ---- phase 3: coalesced float4 output write ----
    {
        float4* ob4 = (float4*)(out + ((size_t)n * FEAT_C + (size_t)ct * C_TILE) * NBINS);
        const float4* so4 = (const float4*)s_out;
        if (tid < (C_TILE * NBINS) / 4)      // 98 threads x 16B
            ob4[tid] = so4[tid];
    }
}

extern "C" void kernel_launch(void* const* d_in, const int* in_sizes, int n_in,
                              void* d_out, int out_size)
{
    const float* feat = (const float*)d_in[0];
    const float* rois = (const float*)d_in[1];
    float* out = (float*)d_out;
    const int N = in_sizes[1] / 5;

    cudaFuncSetAttribute(roi_align_kernel,
                         cudaFuncAttributeMaxDynamicSharedMemorySize,
                         SMEM_TOTAL_BYTES);
    roi_align_kernel<<<N * (FEAT_C / C_TILE), 256, SMEM_TOTAL_BYTES>>>(feat, rois, out);
}

// round 6
// speedup vs baseline: 1.7594x; 1.3313x over previous
#include <cuda_runtime.h>
#include <cuda_bf16.h>
#include <cstdint>

// ROI Align (torchvision semantics), OUT 7x7, adaptive grid <= 4x4.
// features: [B=4, C=256, H=200, W=272] fp32 NCHW
// rois:     [N=512, 5] (b, x1, y1, x2, y2) fp32
// out:      [N, C, 7, 7] fp32
//
// R6: staging via cp.async.bulk (TMA bulk DMA) -- 240 LDGSTS/block -> 240
// per-thread bulk enqueues (8 warp-instructions), completion via mbarrier
// expect_tx. SMEM layout [c][row][36] (CPITCH banks-safe). Compute keeps the
// premultiplied float4 meta tap loop. Slice-major block order for L2 reuse.

#define OUT_H 7
#define OUT_W 7
#define NBINS 49
#define MAXG  4
#define C_TILE 8
#define REG   30               // staged rows per axis
#define WCOLS 36               // staged floats per row (144B, 16B-multiple)
#define CPITCH 1084            // floats per channel: 30*36=1080 +4 pad
                               // 1084*4 % 16 == 0 (bulk dst align), 1084%32==28
                               // -> 8 channel lanes hit 8 distinct banks

#define FEAT_C 256
#define FEAT_H 200
#define FEAT_W 272
#define FEAT_HW (FEAT_H * FEAT_W)

#define STAGE_BYTES (C_TILE * REG * WCOLS * 4)   // 34560

__device__ __forceinline__ uint32_t smem_u32(const void* p) {
    uint32_t a;
    asm("{ .reg .u64 t; cvta.to.shared.u64 t, %1; cvt.u32.u64 %0, t; }"
        : "=r"(a) : "l"(p));
    return a;
}

struct __align__(16) SmemLayout {
    float    region[C_TILE * CPITCH];   // [c][row][36]
    float    s_out[C_TILE * NBINS];
    float4   ymeta[OUT_H * MAXG];       // wy0, wy1, rl*36, rh*36
    float4   xmeta[OUT_H * MAXG];       // wx0, wx1, cl, ch
    unsigned long long mbar;
};

__global__ __launch_bounds__(256)
void roi_align_kernel(const float* __restrict__ feat,
                      const float* __restrict__ rois,
                      float* __restrict__ out)
{
    __shared__ SmemLayout sm;

    const int H = FEAT_H, W = FEAT_W;
    const int blk = blockIdx.x;
    const int n   = blk & 511;        // roi index
    const int ct  = blk >> 9;         // channel tile (slice-major for L2 reuse)

    const float* r = rois + n * 5;
    const int   bidx  = (int)r[0];
    const float x1    = r[1];
    const float y1    = r[2];
    const float roi_w = fmaxf(r[3] - x1, 1.0f);
    const float roi_h = fmaxf(r[4] - y1, 1.0f);
    const float bin_h = roi_h * (1.0f / OUT_H);
    const float bin_w = roi_w * (1.0f / OUT_W);
    int gh = (int)ceilf(roi_h * (1.0f / OUT_H)); gh = min(max(gh, 1), MAXG);
    int gw = (int)ceilf(roi_w * (1.0f / OUT_W)); gw = min(max(gw, 1), MAXG);

    const int ry0 = min(max((int)floorf(y1), 0), H - 1);
    const int rx0 = min(max((int)floorf(x1), 0), W - 1);
    const int ax0 = min(rx0 & ~3, W - WCOLS);   // aligned window, always in-bounds

    const int tid = threadIdx.x;
    const uint32_t mbar = smem_u32(&sm.mbar);

    // ---- init mbarrier + expect full staging byte count ----
    if (tid == 0) {
        asm volatile("mbarrier.init.shared.b64 [%0], 1;" :: "r"(mbar) : "memory");
        asm volatile("mbarrier.arrive.expect_tx.shared.b64 _, [%0], %1;"
                     :: "r"(mbar), "r"(STAGE_BYTES) : "memory");
    }
    __syncthreads();

    // ---- phase 1: enqueue 240 bulk row copies (1 instr per thread) ----
    if (tid < C_TILE * REG) {
        const int c   = tid / REG;
        const int row = tid - c * REG;
        const int gy  = min(ry0 + row, H - 1);
        const float* src = feat
            + ((size_t)bidx * FEAT_C + (size_t)(ct * C_TILE + c)) * (size_t)FEAT_HW
            + (size_t)gy * W + ax0;
        const uint32_t dst = smem_u32(sm.region) + (uint32_t)((c * CPITCH + row * WCOLS) * 4);
        asm volatile(
            "cp.async.bulk.shared::cluster.global.mbarrier::complete_tx::bytes "
            "[%0], [%1], %2, [%3];"
            :: "r"(dst), "l"(src), "r"(WCOLS * 4), "r"(mbar) : "memory");
    }

    // ---- phase 0 (overlapped with DMA): per-axis weights + premult offsets ----
    if (tid < 2 * OUT_H * MAXG) {
        const bool isx = (tid >= OUT_H * MAXG);
        const int  t   = isx ? tid - OUT_H * MAXG : tid;
        const int  p   = t >> 2;          // output bin index along axis
        const int  gg  = t & 3;           // grid slot
        const float start = isx ? x1 : y1;
        const float binsz = isx ? bin_w : bin_h;
        const int   gcnt  = isx ? gw : gh;
        const int   size  = isx ? W : H;
        const float pos = start + (float)p * binsz + ((float)gg + 0.5f) * binsz / (float)gcnt;
        const bool valid = (pos >= -1.0f) && (pos <= (float)size);
        float pp = fmaxf(pos, 0.0f);
        int low = min((int)floorf(pp), size - 1);
        if (low >= size - 1) pp = (float)(size - 1);
        const float frac = pp - (float)low;
        const float m = valid ? 1.0f : 0.0f;
        const int hi = min(low + 1, size - 1);
        float4 mv;
        mv.x = (1.0f - frac) * m;
        mv.y = frac * m;
        if (isx) {
            mv.z = __int_as_float(min(max(low - ax0, 0), WCOLS - 1));
            mv.w = __int_as_float(min(max(hi  - ax0, 0), WCOLS - 1));
            sm.xmeta[t] = mv;
        } else {
            mv.z = __int_as_float(min(max(low - ry0, 0), REG - 1) * WCOLS);
            mv.w = __int_as_float(min(max(hi  - ry0, 0), REG - 1) * WCOLS);
            sm.ymeta[t] = mv;
        }
    }

    // ---- wait for DMA completion (parity 0: fresh barrier every launch) ----
    {
        asm volatile(
            "{\n\t"
            ".reg .pred P;\n\t"
            "WAIT_%=:\n\t"
            "mbarrier.try_wait.parity.acquire.cta.shared::cta.b64 P, [%0], 0, 0x989680;\n\t"
            "@P bra DONE_%=;\n\t"
            "bra WAIT_%=;\n\t"
            "DONE_%=:\n\t"
            "}"
            :: "r"(mbar) : "memory");
    }
    __syncthreads();   // also covers meta visibility

    // ---- phase 2: compute bins from SMEM (packed meta) ----
    {
        const int c   = tid & (C_TILE - 1);
        const int grp = tid >> 3;             // 32 bin groups
        const float inv = 1.0f / (float)max(gh * gw, 1);
        const float* regc = sm.region + c * CPITCH;
        for (int bin = grp; bin < NBINS; bin += 32) {
            const int ph = bin / OUT_W;
            const int pw = bin - ph * OUT_W;
            const float4* ym = sm.ymeta + ph * MAXG;
            const float4* xm = sm.xmeta + pw * MAXG;
            float acc = 0.0f;
            for (int iy = 0; iy < gh; ++iy) {
                const float4 my = ym[iy];
                const float* rlo = regc + __float_as_int(my.z);
                const float* rhi = regc + __float_as_int(my.w);
                for (int ix = 0; ix < gw; ++ix) {
                    const float4 mx = xm[ix];
                    const int cl = __float_as_int(mx.z);
                    const int ch = __float_as_int(mx.w);
                    const float t0 = mx.x * rlo[cl] + mx.y * rlo[ch];
                    const float t1 = mx.x * rhi[cl] + mx.y * rhi[ch];
                    acc += my.x * t0 + my.y * t1;
                }
            }
            sm.s_out[c * NBINS + bin] = acc * inv;
        }
    }
    __syncthreads();

    // ---- phase 3: coalesced float4 output write ----
    {
        float4* ob4 = (float4*)(out + ((size_t)n * FEAT_C + (size_t)ct * C_TILE) * NBINS);
        const float4* so4 = (const float4*)sm.s_out;
        if (tid < (C_TILE * NBINS) / 4)      // 98 threads x 16B
            ob4[tid] = so4[tid];
    }
}

extern "C" void kernel_launch(void* const* d_in, const int* in_sizes, int n_in,
                              void* d_out, int out_size)
{
    const float* feat = (const float*)d_in[0];
    const float* rois = (const float*)d_in[1];
    float* out = (float*)d_out;
    const int N = in_sizes[1] / 5;

    roi_align_kernel<<<N * (FEAT_C / C_TILE), 256>>>(feat, rois, out);
}